// round 12
// baseline (speedup 1.0000x reference)
#include <cuda_runtime.h>
#include <cuda_fp16.h>
#include <math.h>

// Problem constants (fixed shapes per reference)
#define NN 50000
#define EE 800000
#define HH 8
#define HC 256
#define SLOPE 0.2f
#define MPAD 50048   // 391 * 128, padded row count for guard-free GEMM

// ---------------- static device scratch (no allocations allowed) --------------
__device__ __half2 g_h2[MPAD * HC / 2]; // projected features (fp16; rows >= NN garbage, never read)
__device__ __half2 g_o2[MPAD * HC / 2]; // layer output (fp16; rows >= NN stay zero)
__device__ __half  g_Wh2[HC * HC];    // W2 in fp16
__device__ __half  g_Wh3[HC * HC];    // W3 in fp16
__device__ float g_als[NN * HH];      // per-node src attention logits
__device__ float g_ald[NN * HH];      // per-node dst attention logits
__device__ float g_we[HH];            // edge attention weight per head
__device__ int   g_rowptr[NN + 1];
__device__ int   g_cnt[NN];           // zeroed by previous launch's tail (or static init)
__device__ int   g_tmp[NN];           // build cursor (init'd by scan)
__device__ int2  g_edge[EE];          // CSR-ordered (src, edge_attr bits)
__device__ float g_easum[NN];         // sum of incoming edge attr per node
__device__ int   g_bsum[64];
__device__ int   g_bflag[64];         // scan lookback flags (reset by attn tail)
__device__ int   g_barrier;           // grid barrier for scanbuild (reset by attn tail)

// ---------------- helpers ------------------------------------------------------
__device__ __forceinline__ float lrelu(float v) {
    return (v > 0.0f) ? v : SLOPE * v;
}
__device__ __forceinline__ void mma_f16(float* c, const unsigned* a, const unsigned* b) {
    asm volatile(
        "mma.sync.aligned.m16n8k16.row.col.f32.f16.f16.f32 "
        "{%0,%1,%2,%3},{%4,%5,%6,%7},{%8,%9},{%0,%1,%2,%3};"
        : "+f"(c[0]), "+f"(c[1]), "+f"(c[2]), "+f"(c[3])
        : "r"(a[0]), "r"(a[1]), "r"(a[2]), "r"(a[3]), "r"(b[0]), "r"(b[1]));
}
__device__ __forceinline__ void ldsm4(unsigned& r0, unsigned& r1, unsigned& r2,
                                      unsigned& r3, unsigned addr) {
    asm volatile("ldmatrix.sync.aligned.m8n8.x4.shared.b16 {%0,%1,%2,%3},[%4];"
                 : "=r"(r0), "=r"(r1), "=r"(r2), "=r"(r3) : "r"(addr));
}
__device__ __forceinline__ void ldsm4t(unsigned& r0, unsigned& r1, unsigned& r2,
                                       unsigned& r3, unsigned addr) {
    asm volatile("ldmatrix.sync.aligned.m8n8.x4.trans.shared.b16 {%0,%1,%2,%3},[%4];"
                 : "=r"(r0), "=r"(r1), "=r"(r2), "=r"(r3) : "r"(addr));
}
__device__ __forceinline__ void cpasync16(unsigned dst, const void* src) {
    asm volatile("cp.async.ca.shared.global [%0],[%1],16;"
                 :: "r"(dst), "l"(src) : "memory");
}
// f32x2 packed math
__device__ __forceinline__ unsigned long long splat2(float x) {
    unsigned long long r;
    asm("mov.b64 %0,{%1,%1};" : "=l"(r) : "f"(x));
    return r;
}
__device__ __forceinline__ unsigned long long pack2(float x, float y) {
    unsigned long long r;
    asm("mov.b64 %0,{%1,%2};" : "=l"(r) : "f"(x), "f"(y));
    return r;
}
__device__ __forceinline__ unsigned long long fma2(unsigned long long a,
                                                   unsigned long long b,
                                                   unsigned long long c) {
    unsigned long long d;
    asm("fma.rn.f32x2 %0,%1,%2,%3;" : "=l"(d) : "l"(a), "l"(b), "l"(c));
    return d;
}
__device__ __forceinline__ float2 unpk(unsigned long long v) {
    float2 r;
    asm("mov.b64 {%0,%1},%2;" : "=f"(r.x), "=f"(r.y) : "l"(v));
    return r;
}

// ---------------- front kernel: layer-1 logits + g_we + histogram + W cvt -----
#define NA1BLK 1563
#define HISTBLK 3125
#define CVTBLK 512
__global__ void __launch_bounds__(256) k_front(
    const float* __restrict__ x, const float* __restrict__ W1,
    const float* __restrict__ as_, const float* __restrict__ ad_,
    const float* __restrict__ We, const float* __restrict__ ae,
    const int* __restrict__ ei, const float* __restrict__ ea,
    const float* __restrict__ W2, const float* __restrict__ W3) {
    int b = blockIdx.x;
    int t = threadIdx.x;
    if (b >= NA1BLK + HISTBLK) {
        int cb = b - NA1BLK - HISTBLK;          // 0..511
        int idx = (cb & 255) * 256 + t;         // 0..65535
        if (cb < 256) g_Wh2[idx] = __float2half(W2[idx]);
        else          g_Wh3[idx] = __float2half(W3[idx]);
        return;
    }
    if (b >= NA1BLK) {
        int e = (b - NA1BLK) * 256 + t;
        if (e < EE) {
            int d = ei[EE + e];
            atomicAdd(&g_cnt[d], 1);
            atomicAdd(&g_easum[d], ea[e]);
        }
        return;
    }
    __shared__ float svs[4][8], svd[4][8];
    int h = t >> 5, lane = t & 31;
    {
        float asv = as_[t], adv = ad_[t];
#pragma unroll
        for (int k = 0; k < 4; k++) {
            float w = W1[k * 256 + t];
            float s = w * asv, d = w * adv;
            for (int o = 16; o > 0; o >>= 1) {
                s += __shfl_xor_sync(0xffffffffu, s, o);
                d += __shfl_xor_sync(0xffffffffu, d, o);
            }
            if (lane == 0) { svs[k][h] = s; svd[k][h] = d; }
        }
        if (b == 0) {
            float v = We[t] * ae[t];
            for (int o = 16; o > 0; o >>= 1) v += __shfl_xor_sync(0xffffffffu, v, o);
            if (lane == 0) g_we[h] = v;
        }
    }
    __syncthreads();
    int idx = b * 256 + t;
    if (idx >= NN * 8) return;
    int n = idx >> 3, hh = idx & 7;
    float x0 = x[n * 4], x1 = x[n * 4 + 1], x2 = x[n * 4 + 2], x3 = x[n * 4 + 3];
    g_als[idx] = x0 * svs[0][hh] + x1 * svs[1][hh] + x2 * svs[2][hh] + x3 * svs[3][hh];
    g_ald[idx] = x0 * svd[0][hh] + x1 * svd[1][hh] + x2 * svd[2][hh] + x3 * svd[3][hh];
}

// ---------------- fused scan + CSR build (grid barrier; 49 blocks resident) ----
__global__ void k_scanbuild(const int* __restrict__ ei, const float* __restrict__ ea) {
    __shared__ int s[1024];
    __shared__ int s_off;
    int bid = blockIdx.x, tid = threadIdx.x;
    int i = bid * 1024 + tid;
    int v = (i < NN) ? g_cnt[i] : 0;
    s[tid] = v;
    __syncthreads();
    for (int off = 1; off < 1024; off <<= 1) {
        int t = (tid >= off) ? s[tid - off] : 0;
        __syncthreads();
        s[tid] += t;
        __syncthreads();
    }
    if (tid == 1023) {
        g_bsum[bid] = s[1023];
        __threadfence();
        atomicExch(&g_bflag[bid], 1);
    }
    if (tid < 32) {
        int sum = 0;
        for (int p = tid; p < bid; p += 32) {
            while (atomicAdd(&g_bflag[p], 0) == 0) {}
            sum += atomicAdd(&g_bsum[p], 0);
        }
        for (int o = 16; o > 0; o >>= 1) sum += __shfl_xor_sync(0xffffffffu, sum, o);
        if (tid == 0) s_off = sum;
    }
    if (bid == 0 && tid == 0) g_rowptr[NN] = EE;
    __syncthreads();
    if (i < NN) {
        int r = s[tid] - v + s_off;
        g_rowptr[i] = r;
        g_tmp[i] = r;
    }
    __threadfence();
    __syncthreads();
    if (tid == 0) {
        atomicAdd(&g_barrier, 1);
        while (atomicAdd(&g_barrier, 0) < (int)gridDim.x) {}
    }
    __syncthreads();
    int nthr = gridDim.x * 1024;
    for (int e = bid * 1024 + tid; e < EE; e += nthr) {
        int d = ei[EE + e];
        int pos = atomicAdd(&g_tmp[d], 1);
        int2 rec;
        rec.x = ei[e];
        rec.y = __float_as_int(ea[e]);
        g_edge[pos] = rec;
    }
}

// ---------------- layer-1 fused attention (group-parallel, rank-4) ------------
__global__ void __launch_bounds__(256) k_attn1(
    const float* __restrict__ x, const float* __restrict__ W1,
    const float* __restrict__ bias) {
    int warp = (blockIdx.x * blockDim.x + threadIdx.x) >> 5;
    if (warp >= NN) return;
    int n = warp;
    int l = threadIdx.x & 31;
    int g = l >> 3, h = l & 7;

    float we = g_we[h];
    float ald = g_ald[n * 8 + h];
    int start = g_rowptr[n], end = g_rowptr[n + 1];

    float m = -1e30f, psum = 0.0f;
    float4 acc = make_float4(0.f, 0.f, 0.f, 0.f);
    for (int i = start + g; i < end; i += 4) {
        int2 r = g_edge[i];
        int s = r.x;
        float ev = __int_as_float(r.y);
        float al = g_als[s * 8 + h];
        float4 xv = *(const float4*)(x + s * 4);
        float lg = lrelu(al + ald + ev * we);
        float nm = fmaxf(m, lg);
        float sc = __expf(m - nm);
        float p = __expf(lg - nm);
        psum = psum * sc + p;
        acc.x = acc.x * sc + p * xv.x;
        acc.y = acc.y * sc + p * xv.y;
        acc.z = acc.z * sc + p * xv.z;
        acc.w = acc.w * sc + p * xv.w;
        m = nm;
    }
#pragma unroll
    for (int off = 8; off <= 16; off <<= 1) {
        float mo  = __shfl_xor_sync(0xffffffffu, m, off);
        float pso = __shfl_xor_sync(0xffffffffu, psum, off);
        float ax  = __shfl_xor_sync(0xffffffffu, acc.x, off);
        float ay  = __shfl_xor_sync(0xffffffffu, acc.y, off);
        float az  = __shfl_xor_sync(0xffffffffu, acc.z, off);
        float aw  = __shfl_xor_sync(0xffffffffu, acc.w, off);
        float M = fmaxf(m, mo);
        float e1 = __expf(m - M);
        float e2 = __expf(mo - M);
        psum = psum * e1 + pso * e2;
        acc.x = acc.x * e1 + ax * e2;
        acc.y = acc.y * e1 + ay * e2;
        acc.z = acc.z * e1 + az * e2;
        acc.w = acc.w * e1 + aw * e2;
        m = M;
    }

    float inv = 1.0f / (psum + 1e-16f);
    float4 aggv = make_float4(acc.x * inv, acc.y * inv, acc.z * inv, acc.w * inv);
    int src = l >> 2;
    float a0 = __shfl_sync(0xffffffffu, aggv.x, src);
    float a1 = __shfl_sync(0xffffffffu, aggv.y, src);
    float a2 = __shfl_sync(0xffffffffu, aggv.z, src);
    float a3 = __shfl_sync(0xffffffffu, aggv.w, src);

    float o[8];
#pragma unroll
    for (int cc = 0; cc < 8; cc++) {
        int ch = l * 8 + cc;
        float v = fmaf(a0, W1[ch],
                  fmaf(a1, W1[256 + ch],
                  fmaf(a2, W1[512 + ch],
                  fmaf(a3, W1[768 + ch], bias[ch]))));
        o[cc] = fmaxf(v, 0.0f);
    }
    __half2 p0 = __floats2half2_rn(o[0], o[1]);
    __half2 p1 = __floats2half2_rn(o[2], o[3]);
    __half2 p2 = __floats2half2_rn(o[4], o[5]);
    __half2 p3 = __floats2half2_rn(o[6], o[7]);
    uint4 pk;
    pk.x = *(unsigned*)&p0; pk.y = *(unsigned*)&p1;
    pk.z = *(unsigned*)&p2; pk.w = *(unsigned*)&p3;
    __stcs((uint4*)(g_o2 + n * 128 + l * 4), pk);
}

// ---------------- node attention logits for layers 2,3 (warp per node) --------
__global__ void k_nodeatt(const float* __restrict__ as_, const float* __restrict__ ad_,
                          const float* __restrict__ We, const float* __restrict__ ae) {
    if (blockIdx.x == gridDim.x - 1) {
        int t = threadIdx.x;
        int h = t >> 5, lane = t & 31;
        float v = We[t] * ae[t];
        for (int o = 16; o > 0; o >>= 1) v += __shfl_xor_sync(0xffffffffu, v, o);
        if (lane == 0) g_we[h] = v;
        return;
    }
    int warp = (blockIdx.x * blockDim.x + threadIdx.x) >> 5;
    if (warp >= NN) return;
    int n = warp;
    int l = threadIdx.x & 31;
    uint4 hv = *(const uint4*)(g_h2 + n * 128 + l * 4);
    float f[8];
    {
        float2 c0 = __half22float2(*(__half2*)&hv.x);
        float2 c1 = __half22float2(*(__half2*)&hv.y);
        float2 c2 = __half22float2(*(__half2*)&hv.z);
        float2 c3 = __half22float2(*(__half2*)&hv.w);
        f[0] = c0.x; f[1] = c0.y; f[2] = c1.x; f[3] = c1.y;
        f[4] = c2.x; f[5] = c2.y; f[6] = c3.x; f[7] = c3.y;
    }
    const float* asp = as_ + l * 8;
    const float* adp = ad_ + l * 8;
    float s = 0.f, d = 0.f;
#pragma unroll
    for (int q = 0; q < 8; q++) {
        s = fmaf(f[q], asp[q], s);
        d = fmaf(f[q], adp[q], d);
    }
    s += __shfl_xor_sync(0xffffffffu, s, 1);
    s += __shfl_xor_sync(0xffffffffu, s, 2);
    d += __shfl_xor_sync(0xffffffffu, d, 1);
    d += __shfl_xor_sync(0xffffffffu, d, 2);
    if ((l & 3) == 0) {
        g_als[n * 8 + (l >> 2)] = s;
        g_ald[n * 8 + (l >> 2)] = d;
    }
}

// ---------------- FP16 tensor-core GEMM: g_h2 = fp16(g_o2 @ Wh) ----------------
// Block 128x128, k-chunk 64, 2-stage cp.async double buffer, guard-free.
__global__ void __launch_bounds__(256, 2) k_gemm_f16(const __half* __restrict__ Wh) {
    __shared__ __half As[2][128][72];   // [m][k], 144B rows (LDSM conflict-free)
    __shared__ __half Bs[2][64][136];   // [k][n], 272B rows (LDSM conflict-free)
    const __half* A = (const __half*)g_o2;

    int tid = threadIdx.x;
    int rowBase = blockIdx.y * 128;
    int colBase = blockIdx.x * 128;
    int wid = tid >> 5, lane = tid & 31;
    int wm = wid & 3, wn = wid >> 2;            // 4x2 warp grid
    int gid = lane >> 2, tg = lane & 3;

    // staging maps: A 128x64 halves -> 2 thr/row, 32 halves each (4x16B)
    int arow = tid >> 1, ak = (tid & 1) * 32;
    // B 64x128 halves -> 4 thr/row, 32 halves each (4x16B)
    int brow = tid >> 2, bcol = (tid & 3) * 32;
    const __half* Ap = A + (rowBase + arow) * 256 + ak;
    const __half* Bp = Wh + brow * 256 + colBase + bcol;

    unsigned sa[2], sb[2];
#pragma unroll
    for (int f = 0; f < 2; f++) {
        sa[f] = (unsigned)__cvta_generic_to_shared(&As[f][arow][ak]);
        sb[f] = (unsigned)__cvta_generic_to_shared(&Bs[f][brow][bcol]);
    }

    float acc[2][8][4];
#pragma unroll
    for (int i = 0; i < 2; i++)
#pragma unroll
        for (int j = 0; j < 8; j++)
#pragma unroll
            for (int q = 0; q < 4; q++) acc[i][j][q] = 0.0f;

    // prologue: stage chunk 0 into buf 0
#pragma unroll
    for (int u = 0; u < 4; u++) {
        cpasync16(sa[0] + u * 16, Ap + u * 8);
        cpasync16(sb[0] + u * 16, Bp + u * 8);
    }
    asm volatile("cp.async.commit_group;" ::: "memory");

#pragma unroll
    for (int it = 0; it < 4; it++) {
        int cur = it & 1;
        asm volatile("cp.async.wait_group 0;" ::: "memory");
        __syncthreads();
        if (it < 3) {
            int nxt = cur ^ 1;
            const __half* Ap2 = Ap + (it + 1) * 64;
            const __half* Bp2 = Bp + (it + 1) * 64 * 256;
#pragma unroll
            for (int u = 0; u < 4; u++) {
                cpasync16(sa[nxt] + u * 16, Ap2 + u * 8);
                cpasync16(sb[nxt] + u * 16, Bp2 + u * 8);
            }
            asm volatile("cp.async.commit_group;" ::: "memory");
        }
        // compute from buf cur: 4 k-steps of 16
#pragma unroll
        for (int ks = 0; ks < 4; ks++) {
            int k0 = ks * 16;
            unsigned a[2][4];
#pragma unroll
            for (int i = 0; i < 2; i++) {
                int row = wm * 32 + i * 16 + (lane & 15);
                int ko = k0 + ((lane >> 4) << 3);
                unsigned ad = (unsigned)__cvta_generic_to_shared(&As[cur][row][ko]);
                ldsm4(a[i][0], a[i][1], a[i][2], a[i][3], ad);
            }
            unsigned b[8][2];
            {
                int kr = k0 + (lane & 7);
                int nb = ((lane >> 3) << 3);
                unsigned ad0 = (unsigned)__cvta_generic_to_shared(&Bs[cur][kr][wn * 64 + nb]);
                unsigned ad1 = (unsigned)__cvta_generic_to_shared(&Bs[cur][kr][wn * 64 + 32 + nb]);
                int kr2 = kr + 8;
                unsigned ad2 = (unsigned)__cvta_generic_to_shared(&Bs[cur][kr2][wn * 64 + nb]);
                unsigned ad3 = (unsigned)__cvta_generic_to_shared(&Bs[cur][kr2][wn * 64 + 32 + nb]);
                ldsm4t(b[0][0], b[1][0], b[2][0], b[3][0], ad0);
                ldsm4t(b[4][0], b[5][0], b[6][0], b[7][0], ad1);
                ldsm4t(b[0][1], b[1][1], b[2][1], b[3][1], ad2);
                ldsm4t(b[4][1], b[5][1], b[6][1], b[7][1], ad3);
            }
#pragma unroll
            for (int i = 0; i < 2; i++)
#pragma unroll
                for (int j = 0; j < 8; j++) mma_f16(acc[i][j], a[i], b[j]);
        }
    }

    // epilogue -> fp16 g_h2 (guard-free, rows padded)
#pragma unroll
    for (int i = 0; i < 2; i++) {
        int r0 = rowBase + wm * 32 + i * 16 + gid;
        int r1 = r0 + 8;
#pragma unroll
        for (int j = 0; j < 8; j++) {
            int col = colBase + wn * 64 + j * 8 + tg * 2;   // even
            g_h2[r0 * 128 + (col >> 1)] = __floats2half2_rn(acc[i][j][0], acc[i][j][1]);
            g_h2[r1 * 128 + (col >> 1)] = __floats2half2_rn(acc[i][j][2], acc[i][j][3]);
        }
    }
}

// ---------------- fused attention + aggregation (layers 2,3, self-loops) ------
// One warp per dst node, online softmax, unroll-4; fp16 gathers, f32x2 accum.
__global__ void __launch_bounds__(256) k_attn(const float* __restrict__ bias,
                                              float* __restrict__ outp, int reset) {
    int warp = (blockIdx.x * blockDim.x + threadIdx.x) >> 5;
    if (warp >= NN) return;
    int n = warp;
    int l = threadIdx.x & 31;
    int head = l >> 2;

    float we = g_we[head];
    float ald = g_ald[n * 8 + head];
    int start = g_rowptr[n], end = g_rowptr[n + 1];

    float le = g_easum[n] / fmaxf((float)(end - start), 1.0f);
    float m = lrelu(g_als[n * 8 + head] + ald + le * we);
    float psum = 1.0f;
    unsigned long long acc2[4];
    {
        uint4 hv = *(const uint4*)(g_h2 + n * 128 + l * 4);
        const __half2* hp = (const __half2*)&hv;
#pragma unroll
        for (int j = 0; j < 4; j++) {
            float2 c = __half22float2(hp[j]);
            acc2[j] = pack2(c.x, c.y);
        }
    }

    int i = start;
    for (; i + 4 <= end; i += 4) {
        int2 r0 = __ldcs(&g_edge[i]),     r1 = __ldcs(&g_edge[i + 1]);
        int2 r2 = __ldcs(&g_edge[i + 2]), r3 = __ldcs(&g_edge[i + 3]);
        int s0 = r0.x, s1 = r1.x, s2 = r2.x, s3 = r3.x;
        float e0 = __int_as_float(r0.y), e1 = __int_as_float(r1.y);
        float e2 = __int_as_float(r2.y), e3 = __int_as_float(r3.y);
        float al0 = g_als[s0 * 8 + head], al1 = g_als[s1 * 8 + head];
        float al2 = g_als[s2 * 8 + head], al3 = g_als[s3 * 8 + head];
        uint4 v0 = *(const uint4*)(g_h2 + s0 * 128 + l * 4);
        uint4 v1 = *(const uint4*)(g_h2 + s1 * 128 + l * 4);
        uint4 v2 = *(const uint4*)(g_h2 + s2 * 128 + l * 4);
        uint4 v3 = *(const uint4*)(g_h2 + s3 * 128 + l * 4);
        float lg0 = lrelu(al0 + ald + e0 * we);
        float lg1 = lrelu(al1 + ald + e1 * we);
        float lg2 = lrelu(al2 + ald + e2 * we);
        float lg3 = lrelu(al3 + ald + e3 * we);
        float nm = fmaxf(fmaxf(m, fmaxf(lg0, lg1)), fmaxf(lg2, lg3));
        float sc = __expf(m - nm);
        float p0 = __expf(lg0 - nm), p1 = __expf(lg1 - nm);
        float p2 = __expf(lg2 - nm), p3 = __expf(lg3 - nm);
        psum = psum * sc + (p0 + p1) + (p2 + p3);
        unsigned long long sc2 = splat2(sc);
        unsigned long long p02 = splat2(p0), p12 = splat2(p1);
        unsigned long long p22 = splat2(p2), p32 = splat2(p3);
        const __half2* h0 = (const __half2*)&v0;
        const __half2* h1 = (const __half2*)&v1;
        const __half2* h2 = (const __half2*)&v2;
        const __half2* h3 = (const __half2*)&v3;
#pragma unroll
        for (int j = 0; j < 4; j++) {
            float2 c0 = __half22float2(h0[j]);
            float2 c1 = __half22float2(h1[j]);
            float2 c2 = __half22float2(h2[j]);
            float2 c3 = __half22float2(h3[j]);
            unsigned long long w = fma2(pack2(c3.x, c3.y), p32, 0ull);
            w = fma2(pack2(c2.x, c2.y), p22, w);
            w = fma2(pack2(c1.x, c1.y), p12, w);
            w = fma2(pack2(c0.x, c0.y), p02, w);
            acc2[j] = fma2(acc2[j], sc2, w);
        }
        m = nm;
    }
    for (; i < end; i++) {
        int2 r0 = __ldcs(&g_edge[i]);
        int s0 = r0.x;
        float e0 = __int_as_float(r0.y);
        float lg0 = lrelu(g_als[s0 * 8 + head] + ald + e0 * we);
        uint4 v0 = *(const uint4*)(g_h2 + s0 * 128 + l * 4);
        float nm = fmaxf(m, lg0);
        float sc = __expf(m - nm);
        float p0 = __expf(lg0 - nm);
        psum = psum * sc + p0;
        unsigned long long sc2 = splat2(sc), p02 = splat2(p0);
        const __half2* h0 = (const __half2*)&v0;
#pragma unroll
        for (int j = 0; j < 4; j++) {
            float2 c0 = __half22float2(h0[j]);
            unsigned long long w = fma2(pack2(c0.x, c0.y), p02, 0ull);
            acc2[j] = fma2(acc2[j], sc2, w);
        }
        m = nm;
    }

    float inv = 1.0f / (psum + 1e-16f);
    float2 q0 = unpk(acc2[0]), q1 = unpk(acc2[1]);
    float2 q2 = unpk(acc2[2]), q3 = unpk(acc2[3]);
    const float* bp = bias + l * 8;
    float o0 = fmaxf(q0.x * inv + bp[0], 0.f);
    float o1 = fmaxf(q0.y * inv + bp[1], 0.f);
    float o2 = fmaxf(q1.x * inv + bp[2], 0.f);
    float o3 = fmaxf(q1.y * inv + bp[3], 0.f);
    float o4 = fmaxf(q2.x * inv + bp[4], 0.f);
    float o5 = fmaxf(q2.y * inv + bp[5], 0.f);
    float o6 = fmaxf(q3.x * inv + bp[6], 0.f);
    float o7 = fmaxf(q3.y * inv + bp[7], 0.f);
    if (outp) {
        __stcs((float4*)(outp + n * 256 + l * 8),     make_float4(o0, o1, o2, o3));
        __stcs((float4*)(outp + n * 256 + l * 8 + 4), make_float4(o4, o5, o6, o7));
    } else {
        __half2 p0h = __floats2half2_rn(o0, o1);
        __half2 p1h = __floats2half2_rn(o2, o3);
        __half2 p2h = __floats2half2_rn(o4, o5);
        __half2 p3h = __floats2half2_rn(o6, o7);
        uint4 pk;
        pk.x = *(unsigned*)&p0h; pk.y = *(unsigned*)&p1h;
        pk.z = *(unsigned*)&p2h; pk.w = *(unsigned*)&p3h;
        __stcs((uint4*)(g_o2 + n * 128 + l * 4), pk);
    }

    if (reset && l == 0) {
        g_cnt[n] = 0;
        g_easum[n] = 0.0f;
        if (n < 64) g_bflag[n] = 0;
        if (n == 0) g_barrier = 0;
    }
}

// ---------------- launch ------------------------------------------------------
extern "C" void kernel_launch(void* const* d_in, const int* in_sizes, int n_in,
                              void* d_out, int out_size) {
    const float* x   = (const float*)d_in[0];
    const int*   ei  = (const int*)d_in[1];
    const float* ea  = (const float*)d_in[2];
    const float* W1  = (const float*)d_in[3];
    const float* as1 = (const float*)d_in[4];
    const float* ad1 = (const float*)d_in[5];
    const float* We1 = (const float*)d_in[6];
    const float* ae1 = (const float*)d_in[7];
    const float* b1  = (const float*)d_in[8];
    const float* W2  = (const float*)d_in[9];
    const float* as2 = (const float*)d_in[10];
    const float* ad2 = (const float*)d_in[11];
    const float* We2 = (const float*)d_in[12];
    const float* ae2 = (const float*)d_in[13];
    const float* b2  = (const float*)d_in[14];
    const float* W3  = (const float*)d_in[15];
    const float* as3 = (const float*)d_in[16];
    const float* ad3 = (const float*)d_in[17];
    const float* We3 = (const float*)d_in[18];
    const float* ae3 = (const float*)d_in[19];
    const float* b3  = (const float*)d_in[20];
    float* out = (float*)d_out;

    const int scanBlk = (NN + 1023) / 1024;        // 49
    const int attnBlk = (NN * 32 + 255) / 256;     // 6250

    __half* wh2 = nullptr;
    __half* wh3 = nullptr;
    cudaGetSymbolAddress((void**)&wh2, g_Wh2);
    cudaGetSymbolAddress((void**)&wh3, g_Wh3);

    // 0: layer-1 node logits + g_we + histogram + W fp16 conversion
    k_front<<<NA1BLK + HISTBLK + CVTBLK, 256>>>(x, W1, as1, ad1, We1, ae1, ei, ea, W2, W3);
    // 1: fused prefix scan + CSR scatter
    k_scanbuild<<<scanBlk, 1024>>>(ei, ea);
    // 2: layer-1 attention (writes g_o2 fp16)
    k_attn1<<<attnBlk, 256>>>(x, W1, b1);

    dim3 gGemm(2, MPAD / 128);   // (2, 391)

    // layer 2  (3: gemm is the profiled launch)
    k_gemm_f16<<<gGemm, 256>>>(wh2);
    k_nodeatt<<<attnBlk + 1, 256>>>(as2, ad2, We2, ae2);
    k_attn<<<attnBlk, 256>>>(b2, nullptr, 0);

    // layer 3 -> d_out (+ reset counters for next launch)
    k_gemm_f16<<<gGemm, 256>>>(wh3);
    k_nodeatt<<<attnBlk + 1, 256>>>(as3, ad3, We3, ae3);
    k_attn<<<attnBlk, 256>>>(b3, out, 1);
}

// round 13
// speedup vs baseline: 1.1664x; 1.1664x over previous
#include <cuda_runtime.h>
#include <cuda_fp16.h>
#include <math.h>

// Problem constants (fixed shapes per reference)
#define NN 50000
#define EE 800000
#define HH 8
#define HC 256
#define SLOPE 0.2f
#define MPAD 50048   // 391 * 128, padded row count for guard-free GEMM

// ---------------- static device scratch (no allocations allowed) --------------
__device__ __half2 g_h2[MPAD * HC / 2]; // projected features (fp16; rows >= NN garbage, never read)
__device__ __half2 g_o2[MPAD * HC / 2]; // layer output (fp16; rows >= NN stay zero)
__device__ __half  g_Wh2[HC * HC];    // W2 in fp16
__device__ __half  g_Wh3[HC * HC];    // W3 in fp16
__device__ float g_als[MPAD * HH];    // per-node src attention logits (padded)
__device__ float g_ald[MPAD * HH];    // per-node dst attention logits (padded)
__device__ float g_weL[3][HH];        // edge attention weight per head, per layer
__device__ int   g_rowptr[NN + 1];
__device__ int   g_cnt[NN];           // zeroed by previous launch's tail (or static init)
__device__ int   g_tmp[NN];           // build cursor (init'd by scan)
__device__ int2  g_edge[EE];          // CSR-ordered (src, edge_attr bits)
__device__ float g_easum[NN];         // sum of incoming edge attr per node
__device__ int   g_bsum[64];
__device__ int   g_bflag[64];         // scan lookback flags (reset by attn tail)
__device__ int   g_barrier;           // grid barrier for scanbuild (reset by attn tail)

// ---------------- helpers ------------------------------------------------------
__device__ __forceinline__ float lrelu(float v) {
    return (v > 0.0f) ? v : SLOPE * v;
}
__device__ __forceinline__ void mma_f16(float* c, const unsigned* a, const unsigned* b) {
    asm volatile(
        "mma.sync.aligned.m16n8k16.row.col.f32.f16.f16.f32 "
        "{%0,%1,%2,%3},{%4,%5,%6,%7},{%8,%9},{%0,%1,%2,%3};"
        : "+f"(c[0]), "+f"(c[1]), "+f"(c[2]), "+f"(c[3])
        : "r"(a[0]), "r"(a[1]), "r"(a[2]), "r"(a[3]), "r"(b[0]), "r"(b[1]));
}
__device__ __forceinline__ void ldsm4(unsigned& r0, unsigned& r1, unsigned& r2,
                                      unsigned& r3, unsigned addr) {
    asm volatile("ldmatrix.sync.aligned.m8n8.x4.shared.b16 {%0,%1,%2,%3},[%4];"
                 : "=r"(r0), "=r"(r1), "=r"(r2), "=r"(r3) : "r"(addr));
}
__device__ __forceinline__ void ldsm4t(unsigned& r0, unsigned& r1, unsigned& r2,
                                       unsigned& r3, unsigned addr) {
    asm volatile("ldmatrix.sync.aligned.m8n8.x4.trans.shared.b16 {%0,%1,%2,%3},[%4];"
                 : "=r"(r0), "=r"(r1), "=r"(r2), "=r"(r3) : "r"(addr));
}
__device__ __forceinline__ void cpasync16(unsigned dst, const void* src) {
    asm volatile("cp.async.ca.shared.global [%0],[%1],16;"
                 :: "r"(dst), "l"(src) : "memory");
}
// f32x2 packed math
__device__ __forceinline__ unsigned long long splat2(float x) {
    unsigned long long r;
    asm("mov.b64 %0,{%1,%1};" : "=l"(r) : "f"(x));
    return r;
}
__device__ __forceinline__ unsigned long long pack2(float x, float y) {
    unsigned long long r;
    asm("mov.b64 %0,{%1,%2};" : "=l"(r) : "f"(x), "f"(y));
    return r;
}
__device__ __forceinline__ unsigned long long fma2(unsigned long long a,
                                                   unsigned long long b,
                                                   unsigned long long c) {
    unsigned long long d;
    asm("fma.rn.f32x2 %0,%1,%2,%3;" : "=l"(d) : "l"(a), "l"(b), "l"(c));
    return d;
}
__device__ __forceinline__ float2 unpk(unsigned long long v) {
    float2 r;
    asm("mov.b64 {%0,%1},%2;" : "=f"(r.x), "=f"(r.y) : "l"(v));
    return r;
}

// ---------------- front kernel: layer-1 logits + g_we (x3) + histogram + W cvt -
#define NA1BLK 1563
#define HISTBLK 3125
#define CVTBLK 512
__global__ void __launch_bounds__(256) k_front(
    const float* __restrict__ x, const float* __restrict__ W1,
    const float* __restrict__ as_, const float* __restrict__ ad_,
    const float* __restrict__ We1, const float* __restrict__ ae1,
    const float* __restrict__ We2, const float* __restrict__ ae2,
    const float* __restrict__ We3, const float* __restrict__ ae3,
    const int* __restrict__ ei, const float* __restrict__ ea,
    const float* __restrict__ W2, const float* __restrict__ W3) {
    int b = blockIdx.x;
    int t = threadIdx.x;
    if (b >= NA1BLK + HISTBLK) {
        int cb = b - NA1BLK - HISTBLK;          // 0..511
        int idx = (cb & 255) * 256 + t;         // 0..65535
        if (cb < 256) g_Wh2[idx] = __float2half(W2[idx]);
        else          g_Wh3[idx] = __float2half(W3[idx]);
        return;
    }
    if (b >= NA1BLK) {
        int e = (b - NA1BLK) * 256 + t;
        if (e < EE) {
            int d = ei[EE + e];
            atomicAdd(&g_cnt[d], 1);
            atomicAdd(&g_easum[d], ea[e]);
        }
        return;
    }
    __shared__ float svs[4][8], svd[4][8];
    int h = t >> 5, lane = t & 31;
    {
        float asv = as_[t], adv = ad_[t];
#pragma unroll
        for (int k = 0; k < 4; k++) {
            float w = W1[k * 256 + t];
            float s = w * asv, d = w * adv;
            for (int o = 16; o > 0; o >>= 1) {
                s += __shfl_xor_sync(0xffffffffu, s, o);
                d += __shfl_xor_sync(0xffffffffu, d, o);
            }
            if (lane == 0) { svs[k][h] = s; svd[k][h] = d; }
        }
        if (b < 3) {
            const float* Wep = (b == 0) ? We1 : (b == 1) ? We2 : We3;
            const float* aep = (b == 0) ? ae1 : (b == 1) ? ae2 : ae3;
            float v = Wep[t] * aep[t];
            for (int o = 16; o > 0; o >>= 1) v += __shfl_xor_sync(0xffffffffu, v, o);
            if (lane == 0) g_weL[b][h] = v;
        }
    }
    __syncthreads();
    int idx = b * 256 + t;
    if (idx >= NN * 8) return;
    int n = idx >> 3, hh = idx & 7;
    float x0 = x[n * 4], x1 = x[n * 4 + 1], x2 = x[n * 4 + 2], x3 = x[n * 4 + 3];
    g_als[idx] = x0 * svs[0][hh] + x1 * svs[1][hh] + x2 * svs[2][hh] + x3 * svs[3][hh];
    g_ald[idx] = x0 * svd[0][hh] + x1 * svd[1][hh] + x2 * svd[2][hh] + x3 * svd[3][hh];
}

// ---------------- fused scan + CSR build (grid barrier; 49 blocks resident) ----
__global__ void k_scanbuild(const int* __restrict__ ei, const float* __restrict__ ea) {
    __shared__ int s[1024];
    __shared__ int s_off;
    int bid = blockIdx.x, tid = threadIdx.x;
    int i = bid * 1024 + tid;
    int v = (i < NN) ? g_cnt[i] : 0;
    s[tid] = v;
    __syncthreads();
    for (int off = 1; off < 1024; off <<= 1) {
        int t = (tid >= off) ? s[tid - off] : 0;
        __syncthreads();
        s[tid] += t;
        __syncthreads();
    }
    if (tid == 1023) {
        g_bsum[bid] = s[1023];
        __threadfence();
        atomicExch(&g_bflag[bid], 1);
    }
    if (tid < 32) {
        int sum = 0;
        for (int p = tid; p < bid; p += 32) {
            while (atomicAdd(&g_bflag[p], 0) == 0) {}
            sum += atomicAdd(&g_bsum[p], 0);
        }
        for (int o = 16; o > 0; o >>= 1) sum += __shfl_xor_sync(0xffffffffu, sum, o);
        if (tid == 0) s_off = sum;
    }
    if (bid == 0 && tid == 0) g_rowptr[NN] = EE;
    __syncthreads();
    if (i < NN) {
        int r = s[tid] - v + s_off;
        g_rowptr[i] = r;
        g_tmp[i] = r;
    }
    __threadfence();
    __syncthreads();
    if (tid == 0) {
        atomicAdd(&g_barrier, 1);
        while (atomicAdd(&g_barrier, 0) < (int)gridDim.x) {}
    }
    __syncthreads();
    int nthr = gridDim.x * 1024;
    for (int e = bid * 1024 + tid; e < EE; e += nthr) {
        int d = ei[EE + e];
        int pos = atomicAdd(&g_tmp[d], 1);
        int2 rec;
        rec.x = ei[e];
        rec.y = __float_as_int(ea[e]);
        g_edge[pos] = rec;
    }
}

// ---------------- layer-1 fused attention (group-parallel, rank-4) ------------
__global__ void __launch_bounds__(256) k_attn1(
    const float* __restrict__ x, const float* __restrict__ W1,
    const float* __restrict__ bias) {
    int warp = (blockIdx.x * blockDim.x + threadIdx.x) >> 5;
    if (warp >= NN) return;
    int n = warp;
    int l = threadIdx.x & 31;
    int g = l >> 3, h = l & 7;

    float we = g_weL[0][h];
    float ald = g_ald[n * 8 + h];
    int start = g_rowptr[n], end = g_rowptr[n + 1];

    float m = -1e30f, psum = 0.0f;
    float4 acc = make_float4(0.f, 0.f, 0.f, 0.f);
    for (int i = start + g; i < end; i += 4) {
        int2 r = g_edge[i];
        int s = r.x;
        float ev = __int_as_float(r.y);
        float al = g_als[s * 8 + h];
        float4 xv = *(const float4*)(x + s * 4);
        float lg = lrelu(al + ald + ev * we);
        float nm = fmaxf(m, lg);
        float sc = __expf(m - nm);
        float p = __expf(lg - nm);
        psum = psum * sc + p;
        acc.x = acc.x * sc + p * xv.x;
        acc.y = acc.y * sc + p * xv.y;
        acc.z = acc.z * sc + p * xv.z;
        acc.w = acc.w * sc + p * xv.w;
        m = nm;
    }
#pragma unroll
    for (int off = 8; off <= 16; off <<= 1) {
        float mo  = __shfl_xor_sync(0xffffffffu, m, off);
        float pso = __shfl_xor_sync(0xffffffffu, psum, off);
        float ax  = __shfl_xor_sync(0xffffffffu, acc.x, off);
        float ay  = __shfl_xor_sync(0xffffffffu, acc.y, off);
        float az  = __shfl_xor_sync(0xffffffffu, acc.z, off);
        float aw  = __shfl_xor_sync(0xffffffffu, acc.w, off);
        float M = fmaxf(m, mo);
        float e1 = __expf(m - M);
        float e2 = __expf(mo - M);
        psum = psum * e1 + pso * e2;
        acc.x = acc.x * e1 + ax * e2;
        acc.y = acc.y * e1 + ay * e2;
        acc.z = acc.z * e1 + az * e2;
        acc.w = acc.w * e1 + aw * e2;
        m = M;
    }

    float inv = 1.0f / (psum + 1e-16f);
    float4 aggv = make_float4(acc.x * inv, acc.y * inv, acc.z * inv, acc.w * inv);
    int src = l >> 2;
    float a0 = __shfl_sync(0xffffffffu, aggv.x, src);
    float a1 = __shfl_sync(0xffffffffu, aggv.y, src);
    float a2 = __shfl_sync(0xffffffffu, aggv.z, src);
    float a3 = __shfl_sync(0xffffffffu, aggv.w, src);

    float o[8];
#pragma unroll
    for (int cc = 0; cc < 8; cc++) {
        int ch = l * 8 + cc;
        float v = fmaf(a0, W1[ch],
                  fmaf(a1, W1[256 + ch],
                  fmaf(a2, W1[512 + ch],
                  fmaf(a3, W1[768 + ch], bias[ch]))));
        o[cc] = fmaxf(v, 0.0f);
    }
    __half2 p0 = __floats2half2_rn(o[0], o[1]);
    __half2 p1 = __floats2half2_rn(o[2], o[3]);
    __half2 p2 = __floats2half2_rn(o[4], o[5]);
    __half2 p3 = __floats2half2_rn(o[6], o[7]);
    uint4 pk;
    pk.x = *(unsigned*)&p0; pk.y = *(unsigned*)&p1;
    pk.z = *(unsigned*)&p2; pk.w = *(unsigned*)&p3;
    __stcs((uint4*)(g_o2 + n * 128 + l * 4), pk);
}

// ---------------- FP16 tensor-core GEMM + fused node-logit epilogue -----------
// Block 128x128, k-chunk 32, 3-stage cp.async pipeline, guard-free (M padded).
// Epilogue: writes fp16 g_h2 AND g_als/g_ald (dot with as_/ad_ per head, fp32).
__global__ void __launch_bounds__(256, 2) k_gemm_f16(const __half* __restrict__ Wh,
                                                     const float* __restrict__ as_,
                                                     const float* __restrict__ ad_) {
    __shared__ __half As[3][128][40];   // [m][k], 80B rows (LDSM conflict-free)
    __shared__ __half Bs[3][32][136];   // [k][n], 272B rows (LDSM conflict-free)
    const __half* A = (const __half*)g_o2;

    int tid = threadIdx.x;
    int rowBase = blockIdx.y * 128;
    int colBase = blockIdx.x * 128;
    int wid = tid >> 5, lane = tid & 31;
    int wm = wid & 3, wn = wid >> 2;            // 4x2 warp grid
    int gid = lane >> 2, tg = lane & 3;

    int arow = tid >> 1, ak = (tid & 1) * 16;
    int brow = tid >> 3, bcol = (tid & 7) * 16;
    const __half* Ap = A + (rowBase + arow) * 256 + ak;
    const __half* Bp = Wh + brow * 256 + colBase + bcol;

    unsigned sa[3], sb[3];
#pragma unroll
    for (int f = 0; f < 3; f++) {
        sa[f] = (unsigned)__cvta_generic_to_shared(&As[f][arow][ak]);
        sb[f] = (unsigned)__cvta_generic_to_shared(&Bs[f][brow][bcol]);
    }

    float acc[2][8][4];
#pragma unroll
    for (int i = 0; i < 2; i++)
#pragma unroll
        for (int j = 0; j < 8; j++)
#pragma unroll
            for (int q = 0; q < 4; q++) acc[i][j][q] = 0.0f;

    // prologue: stage chunks 0,1
#pragma unroll
    for (int s = 0; s < 2; s++) {
        const __half* Ap2 = Ap + s * 32;
        const __half* Bp2 = Bp + s * 32 * 256;
        cpasync16(sa[s],      Ap2);
        cpasync16(sa[s] + 16, Ap2 + 8);
        cpasync16(sb[s],      Bp2);
        cpasync16(sb[s] + 16, Bp2 + 8);
        asm volatile("cp.async.commit_group;" ::: "memory");
    }

#pragma unroll
    for (int it = 0; it < 8; it++) {
        int cur = it % 3;
        asm volatile("cp.async.wait_group 1;" ::: "memory");
        __syncthreads();
        if (it < 6) {
            int nxt = (it + 2) % 3;
            const __half* Ap2 = Ap + (it + 2) * 32;
            const __half* Bp2 = Bp + (it + 2) * 32 * 256;
            cpasync16(sa[nxt],      Ap2);
            cpasync16(sa[nxt] + 16, Ap2 + 8);
            cpasync16(sb[nxt],      Bp2);
            cpasync16(sb[nxt] + 16, Bp2 + 8);
            asm volatile("cp.async.commit_group;" ::: "memory");
        } else {
            asm volatile("cp.async.commit_group;" ::: "memory");
        }
#pragma unroll
        for (int ks = 0; ks < 2; ks++) {
            int k0 = ks * 16;
            unsigned a[2][4];
#pragma unroll
            for (int i = 0; i < 2; i++) {
                int row = wm * 32 + i * 16 + (lane & 15);
                int ko = k0 + ((lane >> 4) << 3);
                unsigned ad = (unsigned)__cvta_generic_to_shared(&As[cur][row][ko]);
                ldsm4(a[i][0], a[i][1], a[i][2], a[i][3], ad);
            }
            unsigned b[8][2];
            {
                int kr = k0 + (lane & 7);
                int nb = ((lane >> 3) << 3);
                unsigned ad0 = (unsigned)__cvta_generic_to_shared(&Bs[cur][kr][wn * 64 + nb]);
                unsigned ad1 = (unsigned)__cvta_generic_to_shared(&Bs[cur][kr][wn * 64 + 32 + nb]);
                int kr2 = kr + 8;
                unsigned ad2 = (unsigned)__cvta_generic_to_shared(&Bs[cur][kr2][wn * 64 + nb]);
                unsigned ad3 = (unsigned)__cvta_generic_to_shared(&Bs[cur][kr2][wn * 64 + 32 + nb]);
                ldsm4t(b[0][0], b[1][0], b[2][0], b[3][0], ad0);
                ldsm4t(b[4][0], b[5][0], b[6][0], b[7][0], ad1);
                ldsm4t(b[0][1], b[1][1], b[2][1], b[3][1], ad2);
                ldsm4t(b[4][1], b[5][1], b[6][1], b[7][1], ad3);
            }
#pragma unroll
            for (int i = 0; i < 2; i++)
#pragma unroll
                for (int j = 0; j < 8; j++) mma_f16(acc[i][j], a[i], b[j]);
        }
    }

    // epilogue: write fp16 h + fused node-logit dot products
#pragma unroll
    for (int i = 0; i < 2; i++) {
        int r0 = rowBase + wm * 32 + i * 16 + gid;
        int r1 = r0 + 8;
#pragma unroll
        for (int j = 0; j < 8; j++) {
            int col = colBase + wn * 64 + j * 8 + tg * 2;   // even
            g_h2[r0 * 128 + (col >> 1)] = __floats2half2_rn(acc[i][j][0], acc[i][j][1]);
            g_h2[r1 * 128 + (col >> 1)] = __floats2half2_rn(acc[i][j][2], acc[i][j][3]);
        }
        // node-logits: head jh covers j in [jh*4, jh*4+4)
#pragma unroll
        for (int jh = 0; jh < 2; jh++) {
            float sa0 = 0.f, sd0 = 0.f, sa1 = 0.f, sd1 = 0.f;
#pragma unroll
            for (int jj = 0; jj < 4; jj++) {
                int j = jh * 4 + jj;
                int col = colBase + wn * 64 + j * 8 + tg * 2;
                float w0 = as_[col], w1 = as_[col + 1];
                float d0 = ad_[col], d1 = ad_[col + 1];
                sa0 += acc[i][j][0] * w0 + acc[i][j][1] * w1;
                sd0 += acc[i][j][0] * d0 + acc[i][j][1] * d1;
                sa1 += acc[i][j][2] * w0 + acc[i][j][3] * w1;
                sd1 += acc[i][j][2] * d0 + acc[i][j][3] * d1;
            }
            sa0 += __shfl_xor_sync(0xffffffffu, sa0, 1);
            sa0 += __shfl_xor_sync(0xffffffffu, sa0, 2);
            sd0 += __shfl_xor_sync(0xffffffffu, sd0, 1);
            sd0 += __shfl_xor_sync(0xffffffffu, sd0, 2);
            sa1 += __shfl_xor_sync(0xffffffffu, sa1, 1);
            sa1 += __shfl_xor_sync(0xffffffffu, sa1, 2);
            sd1 += __shfl_xor_sync(0xffffffffu, sd1, 1);
            sd1 += __shfl_xor_sync(0xffffffffu, sd1, 2);
            if (tg == 0) {
                int head = (colBase >> 5) + wn * 2 + jh;
                g_als[r0 * 8 + head] = sa0;
                g_ald[r0 * 8 + head] = sd0;
                g_als[r1 * 8 + head] = sa1;
                g_ald[r1 * 8 + head] = sd1;
            }
        }
    }
}

// ---------------- fused attention + aggregation (layers 2,3, self-loops) ------
// One warp per dst node, online softmax, unroll-2 (proven); fp16 gathers,
// f32x2 packed accumulate. layer selects g_weL row.
__global__ void __launch_bounds__(256) k_attn(const float* __restrict__ bias,
                                              float* __restrict__ outp, int layer,
                                              int reset) {
    int warp = (blockIdx.x * blockDim.x + threadIdx.x) >> 5;
    if (warp >= NN) return;
    int n = warp;
    int l = threadIdx.x & 31;
    int head = l >> 2;

    float we = g_weL[layer][head];
    float ald = g_ald[n * 8 + head];
    int start = g_rowptr[n], end = g_rowptr[n + 1];

    float le = g_easum[n] / fmaxf((float)(end - start), 1.0f);
    float m = lrelu(g_als[n * 8 + head] + ald + le * we);
    float psum = 1.0f;
    unsigned long long acc2[4];
    {
        uint4 hv = *(const uint4*)(g_h2 + n * 128 + l * 4);
        const __half2* hp = (const __half2*)&hv;
#pragma unroll
        for (int j = 0; j < 4; j++) {
            float2 c = __half22float2(hp[j]);
            acc2[j] = pack2(c.x, c.y);
        }
    }

    int i = start;
    for (; i + 2 <= end; i += 2) {
        int2 r0 = __ldcs(&g_edge[i]), r1 = __ldcs(&g_edge[i + 1]);
        int s0 = r0.x, s1 = r1.x;
        float e0 = __int_as_float(r0.y), e1 = __int_as_float(r1.y);
        float al0 = g_als[s0 * 8 + head], al1 = g_als[s1 * 8 + head];
        uint4 v0 = *(const uint4*)(g_h2 + s0 * 128 + l * 4);
        uint4 v1 = *(const uint4*)(g_h2 + s1 * 128 + l * 4);
        float lg0 = lrelu(al0 + ald + e0 * we);
        float lg1 = lrelu(al1 + ald + e1 * we);
        float nm = fmaxf(m, fmaxf(lg0, lg1));
        float sc = __expf(m - nm);
        float p0 = __expf(lg0 - nm);
        float p1 = __expf(lg1 - nm);
        psum = psum * sc + p0 + p1;
        unsigned long long sc2 = splat2(sc), p02 = splat2(p0), p12 = splat2(p1);
        const __half2* h0 = (const __half2*)&v0;
        const __half2* h1 = (const __half2*)&v1;
#pragma unroll
        for (int j = 0; j < 4; j++) {
            float2 c0 = __half22float2(h0[j]);
            float2 c1 = __half22float2(h1[j]);
            unsigned long long w = fma2(pack2(c1.x, c1.y), p12, 0ull);
            w = fma2(pack2(c0.x, c0.y), p02, w);
            acc2[j] = fma2(acc2[j], sc2, w);
        }
        m = nm;
    }
    if (i < end) {
        int2 r0 = __ldcs(&g_edge[i]);
        int s0 = r0.x;
        float e0 = __int_as_float(r0.y);
        float lg0 = lrelu(g_als[s0 * 8 + head] + ald + e0 * we);
        uint4 v0 = *(const uint4*)(g_h2 + s0 * 128 + l * 4);
        float nm = fmaxf(m, lg0);
        float sc = __expf(m - nm);
        float p0 = __expf(lg0 - nm);
        psum = psum * sc + p0;
        unsigned long long sc2 = splat2(sc), p02 = splat2(p0);
        const __half2* h0 = (const __half2*)&v0;
#pragma unroll
        for (int j = 0; j < 4; j++) {
            float2 c0 = __half22float2(h0[j]);
            unsigned long long w = fma2(pack2(c0.x, c0.y), p02, 0ull);
            acc2[j] = fma2(acc2[j], sc2, w);
        }
    }

    float inv = 1.0f / (psum + 1e-16f);
    float2 q0 = unpk(acc2[0]), q1 = unpk(acc2[1]);
    float2 q2 = unpk(acc2[2]), q3 = unpk(acc2[3]);
    const float* bp = bias + l * 8;
    float o0 = fmaxf(q0.x * inv + bp[0], 0.f);
    float o1 = fmaxf(q0.y * inv + bp[1], 0.f);
    float o2 = fmaxf(q1.x * inv + bp[2], 0.f);
    float o3 = fmaxf(q1.y * inv + bp[3], 0.f);
    float o4 = fmaxf(q2.x * inv + bp[4], 0.f);
    float o5 = fmaxf(q2.y * inv + bp[5], 0.f);
    float o6 = fmaxf(q3.x * inv + bp[6], 0.f);
    float o7 = fmaxf(q3.y * inv + bp[7], 0.f);
    if (outp) {
        __stcs((float4*)(outp + n * 256 + l * 8),     make_float4(o0, o1, o2, o3));
        __stcs((float4*)(outp + n * 256 + l * 8 + 4), make_float4(o4, o5, o6, o7));
    } else {
        __half2 p0h = __floats2half2_rn(o0, o1);
        __half2 p1h = __floats2half2_rn(o2, o3);
        __half2 p2h = __floats2half2_rn(o4, o5);
        __half2 p3h = __floats2half2_rn(o6, o7);
        uint4 pk;
        pk.x = *(unsigned*)&p0h; pk.y = *(unsigned*)&p1h;
        pk.z = *(unsigned*)&p2h; pk.w = *(unsigned*)&p3h;
        __stcs((uint4*)(g_o2 + n * 128 + l * 4), pk);
    }

    if (reset && l == 0) {
        g_cnt[n] = 0;
        g_easum[n] = 0.0f;
        if (n < 64) g_bflag[n] = 0;
        if (n == 0) g_barrier = 0;
    }
}

// ---------------- launch ------------------------------------------------------
extern "C" void kernel_launch(void* const* d_in, const int* in_sizes, int n_in,
                              void* d_out, int out_size) {
    const float* x   = (const float*)d_in[0];
    const int*   ei  = (const int*)d_in[1];
    const float* ea  = (const float*)d_in[2];
    const float* W1  = (const float*)d_in[3];
    const float* as1 = (const float*)d_in[4];
    const float* ad1 = (const float*)d_in[5];
    const float* We1 = (const float*)d_in[6];
    const float* ae1 = (const float*)d_in[7];
    const float* b1  = (const float*)d_in[8];
    const float* W2  = (const float*)d_in[9];
    const float* as2 = (const float*)d_in[10];
    const float* ad2 = (const float*)d_in[11];
    const float* We2 = (const float*)d_in[12];
    const float* ae2 = (const float*)d_in[13];
    const float* b2  = (const float*)d_in[14];
    const float* W3  = (const float*)d_in[15];
    const float* as3 = (const float*)d_in[16];
    const float* ad3 = (const float*)d_in[17];
    const float* We3 = (const float*)d_in[18];
    const float* ae3 = (const float*)d_in[19];
    const float* b3  = (const float*)d_in[20];
    float* out = (float*)d_out;

    const int scanBlk = (NN + 1023) / 1024;        // 49
    const int attnBlk = (NN * 32 + 255) / 256;     // 6250

    __half* wh2 = nullptr;
    __half* wh3 = nullptr;
    cudaGetSymbolAddress((void**)&wh2, g_Wh2);
    cudaGetSymbolAddress((void**)&wh3, g_Wh3);

    // 0: layer-1 node logits + g_we (x3) + histogram + W fp16 conversion
    k_front<<<NA1BLK + HISTBLK + CVTBLK, 256>>>(x, W1, as1, ad1,
                                               We1, ae1, We2, ae2, We3, ae3,
                                               ei, ea, W2, W3);
    // 1: fused prefix scan + CSR scatter
    k_scanbuild<<<scanBlk, 1024>>>(ei, ea);
    // 2: layer-1 attention (writes g_o2 fp16)
    k_attn1<<<attnBlk, 256>>>(x, W1, b1);

    dim3 gGemm(2, MPAD / 128);   // (2, 391)

    // layer 2  (3: gemm is the profiled launch; epilogue writes g_als/g_ald)
    k_gemm_f16<<<gGemm, 256>>>(wh2, as2, ad2);
    k_attn<<<attnBlk, 256>>>(b2, nullptr, 1, 0);

    // layer 3 -> d_out (+ reset counters for next launch)
    k_gemm_f16<<<gGemm, 256>>>(wh3, as3, ad3);
    k_attn<<<attnBlk, 256>>>(b3, out, 2, 1);
}

// round 14
// speedup vs baseline: 1.2013x; 1.0299x over previous
#include <cuda_runtime.h>
#include <cuda_fp16.h>
#include <math.h>

// Problem constants (fixed shapes per reference)
#define NN 50000
#define EE 800000
#define HH 8
#define HC 256
#define SLOPE 0.2f
#define MPAD 50048   // 391 * 128, padded row count for guard-free GEMM

// ---------------- static device scratch (no allocations allowed) --------------
__device__ __half2 g_h2[MPAD * HC / 2]; // projected features (fp16; rows >= NN garbage, never read)
__device__ __half2 g_o2[MPAD * HC / 2]; // layer output (fp16; rows >= NN stay zero)
__device__ __half  g_Wh2[HC * HC];    // W2 in fp16
__device__ __half  g_Wh3[HC * HC];    // W3 in fp16
__device__ float g_als[MPAD * HH];    // per-node src attention logits (padded)
__device__ float g_ald[MPAD * HH];    // per-node dst attention logits (padded)
__device__ float g_weL[3][HH];        // edge attention weight per head, per layer
__device__ int   g_rowptr[NN + 1];
__device__ int   g_cnt[NN];           // zeroed by previous launch's tail (or static init)
__device__ int   g_tmp[NN];           // build cursor (init'd by scan)
__device__ int2  g_edge[EE];          // CSR-ordered (src, edge_attr bits)
__device__ int   g_bsum[64];
__device__ int   g_bflag[64];         // scan lookback flags (reset by attn tail)
__device__ int   g_barrier;           // grid barrier for scanbuild (reset by attn tail)

// ---------------- helpers ------------------------------------------------------
__device__ __forceinline__ float lrelu(float v) {
    return (v > 0.0f) ? v : SLOPE * v;
}
__device__ __forceinline__ float expc(float v) {   // overflow-guarded exp
    return __expf(fminf(v, 80.0f));
}
__device__ __forceinline__ void mma_f16(float* c, const unsigned* a, const unsigned* b) {
    asm volatile(
        "mma.sync.aligned.m16n8k16.row.col.f32.f16.f16.f32 "
        "{%0,%1,%2,%3},{%4,%5,%6,%7},{%8,%9},{%0,%1,%2,%3};"
        : "+f"(c[0]), "+f"(c[1]), "+f"(c[2]), "+f"(c[3])
        : "r"(a[0]), "r"(a[1]), "r"(a[2]), "r"(a[3]), "r"(b[0]), "r"(b[1]));
}
__device__ __forceinline__ void ldsm4(unsigned& r0, unsigned& r1, unsigned& r2,
                                      unsigned& r3, unsigned addr) {
    asm volatile("ldmatrix.sync.aligned.m8n8.x4.shared.b16 {%0,%1,%2,%3},[%4];"
                 : "=r"(r0), "=r"(r1), "=r"(r2), "=r"(r3) : "r"(addr));
}
__device__ __forceinline__ void ldsm4t(unsigned& r0, unsigned& r1, unsigned& r2,
                                       unsigned& r3, unsigned addr) {
    asm volatile("ldmatrix.sync.aligned.m8n8.x4.trans.shared.b16 {%0,%1,%2,%3},[%4];"
                 : "=r"(r0), "=r"(r1), "=r"(r2), "=r"(r3) : "r"(addr));
}
__device__ __forceinline__ void cpasync16(unsigned dst, const void* src) {
    asm volatile("cp.async.ca.shared.global [%0],[%1],16;"
                 :: "r"(dst), "l"(src) : "memory");
}
// f32x2 packed math
__device__ __forceinline__ unsigned long long splat2(float x) {
    unsigned long long r;
    asm("mov.b64 %0,{%1,%1};" : "=l"(r) : "f"(x));
    return r;
}
__device__ __forceinline__ unsigned long long pack2(float x, float y) {
    unsigned long long r;
    asm("mov.b64 %0,{%1,%2};" : "=l"(r) : "f"(x), "f"(y));
    return r;
}
__device__ __forceinline__ unsigned long long fma2(unsigned long long a,
                                                   unsigned long long b,
                                                   unsigned long long c) {
    unsigned long long d;
    asm("fma.rn.f32x2 %0,%1,%2,%3;" : "=l"(d) : "l"(a), "l"(b), "l"(c));
    return d;
}
__device__ __forceinline__ float2 unpk(unsigned long long v) {
    float2 r;
    asm("mov.b64 {%0,%1},%2;" : "=f"(r.x), "=f"(r.y) : "l"(v));
    return r;
}

// ---------------- front kernel: layer-1 logits + g_we (x3) + histogram + W cvt -
#define NA1BLK 1563
#define HISTBLK 3125
#define CVTBLK 512
__global__ void __launch_bounds__(256) k_front(
    const float* __restrict__ x, const float* __restrict__ W1,
    const float* __restrict__ as_, const float* __restrict__ ad_,
    const float* __restrict__ We1, const float* __restrict__ ae1,
    const float* __restrict__ We2, const float* __restrict__ ae2,
    const float* __restrict__ We3, const float* __restrict__ ae3,
    const int* __restrict__ ei,
    const float* __restrict__ W2, const float* __restrict__ W3) {
    int b = blockIdx.x;
    int t = threadIdx.x;
    if (b >= NA1BLK + HISTBLK) {
        int cb = b - NA1BLK - HISTBLK;          // 0..511
        int idx = (cb & 255) * 256 + t;         // 0..65535
        if (cb < 256) g_Wh2[idx] = __float2half(W2[idx]);
        else          g_Wh3[idx] = __float2half(W3[idx]);
        return;
    }
    if (b >= NA1BLK) {
        int e = (b - NA1BLK) * 256 + t;
        if (e < EE) {
            int d = ei[EE + e];
            atomicAdd(&g_cnt[d], 1);
        }
        return;
    }
    __shared__ float svs[4][8], svd[4][8];
    int h = t >> 5, lane = t & 31;
    {
        float asv = as_[t], adv = ad_[t];
#pragma unroll
        for (int k = 0; k < 4; k++) {
            float w = W1[k * 256 + t];
            float s = w * asv, d = w * adv;
            for (int o = 16; o > 0; o >>= 1) {
                s += __shfl_xor_sync(0xffffffffu, s, o);
                d += __shfl_xor_sync(0xffffffffu, d, o);
            }
            if (lane == 0) { svs[k][h] = s; svd[k][h] = d; }
        }
        if (b < 3) {
            const float* Wep = (b == 0) ? We1 : (b == 1) ? We2 : We3;
            const float* aep = (b == 0) ? ae1 : (b == 1) ? ae2 : ae3;
            float v = Wep[t] * aep[t];
            for (int o = 16; o > 0; o >>= 1) v += __shfl_xor_sync(0xffffffffu, v, o);
            if (lane == 0) g_weL[b][h] = v;
        }
    }
    __syncthreads();
    int idx = b * 256 + t;
    if (idx >= NN * 8) return;
    int n = idx >> 3, hh = idx & 7;
    float x0 = x[n * 4], x1 = x[n * 4 + 1], x2 = x[n * 4 + 2], x3 = x[n * 4 + 3];
    g_als[idx] = x0 * svs[0][hh] + x1 * svs[1][hh] + x2 * svs[2][hh] + x3 * svs[3][hh];
    g_ald[idx] = x0 * svd[0][hh] + x1 * svd[1][hh] + x2 * svd[2][hh] + x3 * svd[3][hh];
}

// ---------------- fused scan + CSR build (grid barrier; 49 blocks resident) ----
__global__ void k_scanbuild(const int* __restrict__ ei, const float* __restrict__ ea) {
    __shared__ int s[1024];
    __shared__ int s_off;
    int bid = blockIdx.x, tid = threadIdx.x;
    int i = bid * 1024 + tid;
    int v = (i < NN) ? g_cnt[i] : 0;
    s[tid] = v;
    __syncthreads();
    for (int off = 1; off < 1024; off <<= 1) {
        int t = (tid >= off) ? s[tid - off] : 0;
        __syncthreads();
        s[tid] += t;
        __syncthreads();
    }
    if (tid == 1023) {
        g_bsum[bid] = s[1023];
        __threadfence();
        atomicExch(&g_bflag[bid], 1);
    }
    if (tid < 32) {
        int sum = 0;
        for (int p = tid; p < bid; p += 32) {
            while (atomicAdd(&g_bflag[p], 0) == 0) {}
            sum += atomicAdd(&g_bsum[p], 0);
        }
        for (int o = 16; o > 0; o >>= 1) sum += __shfl_xor_sync(0xffffffffu, sum, o);
        if (tid == 0) s_off = sum;
    }
    if (bid == 0 && tid == 0) g_rowptr[NN] = EE;
    __syncthreads();
    if (i < NN) {
        int r = s[tid] - v + s_off;
        g_rowptr[i] = r;
        g_tmp[i] = r;
    }
    __threadfence();
    __syncthreads();
    if (tid == 0) {
        atomicAdd(&g_barrier, 1);
        while (atomicAdd(&g_barrier, 0) < (int)gridDim.x) {}
    }
    __syncthreads();
    int nthr = gridDim.x * 1024;
    for (int e = bid * 1024 + tid; e < EE; e += nthr) {
        int d = ei[EE + e];
        int pos = atomicAdd(&g_tmp[d], 1);
        int2 rec;
        rec.x = ei[e];
        rec.y = __float_as_int(ea[e]);
        g_edge[pos] = rec;
    }
}

// ---------------- layer-1 fused attention (group-parallel, rank-4, no-max) ----
__global__ void __launch_bounds__(256) k_attn1(
    const float* __restrict__ x, const float* __restrict__ W1,
    const float* __restrict__ bias) {
    int warp = (blockIdx.x * blockDim.x + threadIdx.x) >> 5;
    if (warp >= NN) return;
    int n = warp;
    int l = threadIdx.x & 31;
    int g = l >> 3, h = l & 7;

    float we = g_weL[0][h];
    float ald = g_ald[n * 8 + h];
    int start = g_rowptr[n], end = g_rowptr[n + 1];

    float psum = 0.0f;
    float4 acc = make_float4(0.f, 0.f, 0.f, 0.f);
    for (int i = start + g; i < end; i += 4) {
        int2 r = g_edge[i];
        int s = r.x;
        float ev = __int_as_float(r.y);
        float al = g_als[s * 8 + h];
        float4 xv = *(const float4*)(x + s * 4);
        float p = expc(lrelu(al + ald + ev * we));
        psum += p;
        acc.x = fmaf(p, xv.x, acc.x);
        acc.y = fmaf(p, xv.y, acc.y);
        acc.z = fmaf(p, xv.z, acc.z);
        acc.w = fmaf(p, xv.w, acc.w);
    }
    // merge across the 4 groups (plain sums)
#pragma unroll
    for (int off = 8; off <= 16; off <<= 1) {
        psum  += __shfl_xor_sync(0xffffffffu, psum, off);
        acc.x += __shfl_xor_sync(0xffffffffu, acc.x, off);
        acc.y += __shfl_xor_sync(0xffffffffu, acc.y, off);
        acc.z += __shfl_xor_sync(0xffffffffu, acc.z, off);
        acc.w += __shfl_xor_sync(0xffffffffu, acc.w, off);
    }

    float inv = 1.0f / (psum + 1e-16f);
    float4 aggv = make_float4(acc.x * inv, acc.y * inv, acc.z * inv, acc.w * inv);
    int src = l >> 2;
    float a0 = __shfl_sync(0xffffffffu, aggv.x, src);
    float a1 = __shfl_sync(0xffffffffu, aggv.y, src);
    float a2 = __shfl_sync(0xffffffffu, aggv.z, src);
    float a3 = __shfl_sync(0xffffffffu, aggv.w, src);

    float o[8];
#pragma unroll
    for (int cc = 0; cc < 8; cc++) {
        int ch = l * 8 + cc;
        float v = fmaf(a0, W1[ch],
                  fmaf(a1, W1[256 + ch],
                  fmaf(a2, W1[512 + ch],
                  fmaf(a3, W1[768 + ch], bias[ch]))));
        o[cc] = fmaxf(v, 0.0f);
    }
    __half2 p0 = __floats2half2_rn(o[0], o[1]);
    __half2 p1 = __floats2half2_rn(o[2], o[3]);
    __half2 p2 = __floats2half2_rn(o[4], o[5]);
    __half2 p3 = __floats2half2_rn(o[6], o[7]);
    uint4 pk;
    pk.x = *(unsigned*)&p0; pk.y = *(unsigned*)&p1;
    pk.z = *(unsigned*)&p2; pk.w = *(unsigned*)&p3;
    __stcs((uint4*)(g_o2 + n * 128 + l * 4), pk);
}

// ---------------- FP16 tensor-core GEMM + fused node-logit epilogue -----------
__global__ void __launch_bounds__(256, 2) k_gemm_f16(const __half* __restrict__ Wh,
                                                     const float* __restrict__ as_,
                                                     const float* __restrict__ ad_) {
    __shared__ __half As[3][128][40];   // [m][k], 80B rows (LDSM conflict-free)
    __shared__ __half Bs[3][32][136];   // [k][n], 272B rows (LDSM conflict-free)
    const __half* A = (const __half*)g_o2;

    int tid = threadIdx.x;
    int rowBase = blockIdx.y * 128;
    int colBase = blockIdx.x * 128;
    int wid = tid >> 5, lane = tid & 31;
    int wm = wid & 3, wn = wid >> 2;            // 4x2 warp grid
    int gid = lane >> 2, tg = lane & 3;

    int arow = tid >> 1, ak = (tid & 1) * 16;
    int brow = tid >> 3, bcol = (tid & 7) * 16;
    const __half* Ap = A + (rowBase + arow) * 256 + ak;
    const __half* Bp = Wh + brow * 256 + colBase + bcol;

    unsigned sa[3], sb[3];
#pragma unroll
    for (int f = 0; f < 3; f++) {
        sa[f] = (unsigned)__cvta_generic_to_shared(&As[f][arow][ak]);
        sb[f] = (unsigned)__cvta_generic_to_shared(&Bs[f][brow][bcol]);
    }

    float acc[2][8][4];
#pragma unroll
    for (int i = 0; i < 2; i++)
#pragma unroll
        for (int j = 0; j < 8; j++)
#pragma unroll
            for (int q = 0; q < 4; q++) acc[i][j][q] = 0.0f;

#pragma unroll
    for (int s = 0; s < 2; s++) {
        const __half* Ap2 = Ap + s * 32;
        const __half* Bp2 = Bp + s * 32 * 256;
        cpasync16(sa[s],      Ap2);
        cpasync16(sa[s] + 16, Ap2 + 8);
        cpasync16(sb[s],      Bp2);
        cpasync16(sb[s] + 16, Bp2 + 8);
        asm volatile("cp.async.commit_group;" ::: "memory");
    }

#pragma unroll
    for (int it = 0; it < 8; it++) {
        int cur = it % 3;
        asm volatile("cp.async.wait_group 1;" ::: "memory");
        __syncthreads();
        if (it < 6) {
            int nxt = (it + 2) % 3;
            const __half* Ap2 = Ap + (it + 2) * 32;
            const __half* Bp2 = Bp + (it + 2) * 32 * 256;
            cpasync16(sa[nxt],      Ap2);
            cpasync16(sa[nxt] + 16, Ap2 + 8);
            cpasync16(sb[nxt],      Bp2);
            cpasync16(sb[nxt] + 16, Bp2 + 8);
            asm volatile("cp.async.commit_group;" ::: "memory");
        } else {
            asm volatile("cp.async.commit_group;" ::: "memory");
        }
#pragma unroll
        for (int ks = 0; ks < 2; ks++) {
            int k0 = ks * 16;
            unsigned a[2][4];
#pragma unroll
            for (int i = 0; i < 2; i++) {
                int row = wm * 32 + i * 16 + (lane & 15);
                int ko = k0 + ((lane >> 4) << 3);
                unsigned ad = (unsigned)__cvta_generic_to_shared(&As[cur][row][ko]);
                ldsm4(a[i][0], a[i][1], a[i][2], a[i][3], ad);
            }
            unsigned b[8][2];
            {
                int kr = k0 + (lane & 7);
                int nb = ((lane >> 3) << 3);
                unsigned ad0 = (unsigned)__cvta_generic_to_shared(&Bs[cur][kr][wn * 64 + nb]);
                unsigned ad1 = (unsigned)__cvta_generic_to_shared(&Bs[cur][kr][wn * 64 + 32 + nb]);
                int kr2 = kr + 8;
                unsigned ad2 = (unsigned)__cvta_generic_to_shared(&Bs[cur][kr2][wn * 64 + nb]);
                unsigned ad3 = (unsigned)__cvta_generic_to_shared(&Bs[cur][kr2][wn * 64 + 32 + nb]);
                ldsm4t(b[0][0], b[1][0], b[2][0], b[3][0], ad0);
                ldsm4t(b[4][0], b[5][0], b[6][0], b[7][0], ad1);
                ldsm4t(b[0][1], b[1][1], b[2][1], b[3][1], ad2);
                ldsm4t(b[4][1], b[5][1], b[6][1], b[7][1], ad3);
            }
#pragma unroll
            for (int i = 0; i < 2; i++)
#pragma unroll
                for (int j = 0; j < 8; j++) mma_f16(acc[i][j], a[i], b[j]);
        }
    }

    // epilogue: write fp16 h + fused node-logit dot products
#pragma unroll
    for (int i = 0; i < 2; i++) {
        int r0 = rowBase + wm * 32 + i * 16 + gid;
        int r1 = r0 + 8;
#pragma unroll
        for (int j = 0; j < 8; j++) {
            int col = colBase + wn * 64 + j * 8 + tg * 2;   // even
            g_h2[r0 * 128 + (col >> 1)] = __floats2half2_rn(acc[i][j][0], acc[i][j][1]);
            g_h2[r1 * 128 + (col >> 1)] = __floats2half2_rn(acc[i][j][2], acc[i][j][3]);
        }
#pragma unroll
        for (int jh = 0; jh < 2; jh++) {
            float sa0 = 0.f, sd0 = 0.f, sa1 = 0.f, sd1 = 0.f;
#pragma unroll
            for (int jj = 0; jj < 4; jj++) {
                int j = jh * 4 + jj;
                int col = colBase + wn * 64 + j * 8 + tg * 2;
                float w0 = as_[col], w1 = as_[col + 1];
                float d0 = ad_[col], d1 = ad_[col + 1];
                sa0 += acc[i][j][0] * w0 + acc[i][j][1] * w1;
                sd0 += acc[i][j][0] * d0 + acc[i][j][1] * d1;
                sa1 += acc[i][j][2] * w0 + acc[i][j][3] * w1;
                sd1 += acc[i][j][2] * d0 + acc[i][j][3] * d1;
            }
            sa0 += __shfl_xor_sync(0xffffffffu, sa0, 1);
            sa0 += __shfl_xor_sync(0xffffffffu, sa0, 2);
            sd0 += __shfl_xor_sync(0xffffffffu, sd0, 1);
            sd0 += __shfl_xor_sync(0xffffffffu, sd0, 2);
            sa1 += __shfl_xor_sync(0xffffffffu, sa1, 1);
            sa1 += __shfl_xor_sync(0xffffffffu, sa1, 2);
            sd1 += __shfl_xor_sync(0xffffffffu, sd1, 1);
            sd1 += __shfl_xor_sync(0xffffffffu, sd1, 2);
            if (tg == 0) {
                int head = (colBase >> 5) + wn * 2 + jh;
                g_als[r0 * 8 + head] = sa0;
                g_ald[r0 * 8 + head] = sd0;
                g_als[r1 * 8 + head] = sa1;
                g_ald[r1 * 8 + head] = sd1;
            }
        }
    }
}

// ---------------- fused attention + aggregation (layers 2,3, no-max softmax) --
// One warp per dst node, unroll-2; fp16 gathers, f32x2 accumulate.
// easum accumulated in-loop; self-loop term added after the loop.
__global__ void __launch_bounds__(256) k_attn(const float* __restrict__ bias,
                                              float* __restrict__ outp, int layer,
                                              int reset) {
    int warp = (blockIdx.x * blockDim.x + threadIdx.x) >> 5;
    if (warp >= NN) return;
    int n = warp;
    int l = threadIdx.x & 31;
    int head = l >> 2;

    float we = g_weL[layer][head];
    float ald = g_ald[n * 8 + head];
    int start = g_rowptr[n], end = g_rowptr[n + 1];

    float psum = 0.0f, easum = 0.0f;
    unsigned long long acc2[4] = {0ull, 0ull, 0ull, 0ull};

    int i = start;
    for (; i + 2 <= end; i += 2) {
        int2 r0 = __ldcs(&g_edge[i]), r1 = __ldcs(&g_edge[i + 1]);
        int s0 = r0.x, s1 = r1.x;
        float e0 = __int_as_float(r0.y), e1 = __int_as_float(r1.y);
        float al0 = g_als[s0 * 8 + head], al1 = g_als[s1 * 8 + head];
        uint4 v0 = *(const uint4*)(g_h2 + s0 * 128 + l * 4);
        uint4 v1 = *(const uint4*)(g_h2 + s1 * 128 + l * 4);
        float p0 = expc(lrelu(al0 + ald + e0 * we));
        float p1 = expc(lrelu(al1 + ald + e1 * we));
        psum += p0 + p1;
        easum += e0 + e1;
        unsigned long long p02 = splat2(p0), p12 = splat2(p1);
        const __half2* h0 = (const __half2*)&v0;
        const __half2* h1 = (const __half2*)&v1;
#pragma unroll
        for (int j = 0; j < 4; j++) {
            float2 c0 = __half22float2(h0[j]);
            float2 c1 = __half22float2(h1[j]);
            acc2[j] = fma2(pack2(c0.x, c0.y), p02, acc2[j]);
            acc2[j] = fma2(pack2(c1.x, c1.y), p12, acc2[j]);
        }
    }
    if (i < end) {
        int2 r0 = __ldcs(&g_edge[i]);
        int s0 = r0.x;
        float e0 = __int_as_float(r0.y);
        uint4 v0 = *(const uint4*)(g_h2 + s0 * 128 + l * 4);
        float p0 = expc(lrelu(g_als[s0 * 8 + head] + ald + e0 * we));
        psum += p0;
        easum += e0;
        unsigned long long p02 = splat2(p0);
        const __half2* h0 = (const __half2*)&v0;
#pragma unroll
        for (int j = 0; j < 4; j++) {
            float2 c0 = __half22float2(h0[j]);
            acc2[j] = fma2(pack2(c0.x, c0.y), p02, acc2[j]);
        }
    }

    // self-loop (fill_value='mean') added post-loop
    {
        float le = easum / fmaxf((float)(end - start), 1.0f);
        float ps = expc(lrelu(g_als[n * 8 + head] + ald + le * we));
        psum += ps;
        unsigned long long ps2 = splat2(ps);
        uint4 hv = *(const uint4*)(g_h2 + n * 128 + l * 4);
        const __half2* hp = (const __half2*)&hv;
#pragma unroll
        for (int j = 0; j < 4; j++) {
            float2 c = __half22float2(hp[j]);
            acc2[j] = fma2(pack2(c.x, c.y), ps2, acc2[j]);
        }
    }

    float inv = 1.0f / (psum + 1e-16f);
    float2 q0 = unpk(acc2[0]), q1 = unpk(acc2[1]);
    float2 q2 = unpk(acc2[2]), q3 = unpk(acc2[3]);
    const float* bp = bias + l * 8;
    float o0 = fmaxf(q0.x * inv + bp[0], 0.f);
    float o1 = fmaxf(q0.y * inv + bp[1], 0.f);
    float o2 = fmaxf(q1.x * inv + bp[2], 0.f);
    float o3 = fmaxf(q1.y * inv + bp[3], 0.f);
    float o4 = fmaxf(q2.x * inv + bp[4], 0.f);
    float o5 = fmaxf(q2.y * inv + bp[5], 0.f);
    float o6 = fmaxf(q3.x * inv + bp[6], 0.f);
    float o7 = fmaxf(q3.y * inv + bp[7], 0.f);
    if (outp) {
        __stcs((float4*)(outp + n * 256 + l * 8),     make_float4(o0, o1, o2, o3));
        __stcs((float4*)(outp + n * 256 + l * 8 + 4), make_float4(o4, o5, o6, o7));
    } else {
        __half2 p0h = __floats2half2_rn(o0, o1);
        __half2 p1h = __floats2half2_rn(o2, o3);
        __half2 p2h = __floats2half2_rn(o4, o5);
        __half2 p3h = __floats2half2_rn(o6, o7);
        uint4 pk;
        pk.x = *(unsigned*)&p0h; pk.y = *(unsigned*)&p1h;
        pk.z = *(unsigned*)&p2h; pk.w = *(unsigned*)&p3h;
        __stcs((uint4*)(g_o2 + n * 128 + l * 4), pk);
    }

    if (reset && l == 0) {
        g_cnt[n] = 0;
        if (n < 64) g_bflag[n] = 0;
        if (n == 0) g_barrier = 0;
    }
}

// ---------------- launch ------------------------------------------------------
extern "C" void kernel_launch(void* const* d_in, const int* in_sizes, int n_in,
                              void* d_out, int out_size) {
    const float* x   = (const float*)d_in[0];
    const int*   ei  = (const int*)d_in[1];
    const float* ea  = (const float*)d_in[2];
    const float* W1  = (const float*)d_in[3];
    const float* as1 = (const float*)d_in[4];
    const float* ad1 = (const float*)d_in[5];
    const float* We1 = (const float*)d_in[6];
    const float* ae1 = (const float*)d_in[7];
    const float* b1  = (const float*)d_in[8];
    const float* W2  = (const float*)d_in[9];
    const float* as2 = (const float*)d_in[10];
    const float* ad2 = (const float*)d_in[11];
    const float* We2 = (const float*)d_in[12];
    const float* ae2 = (const float*)d_in[13];
    const float* b2  = (const float*)d_in[14];
    const float* W3  = (const float*)d_in[15];
    const float* as3 = (const float*)d_in[16];
    const float* ad3 = (const float*)d_in[17];
    const float* We3 = (const float*)d_in[18];
    const float* ae3 = (const float*)d_in[19];
    const float* b3  = (const float*)d_in[20];
    float* out = (float*)d_out;

    const int scanBlk = (NN + 1023) / 1024;        // 49
    const int attnBlk = (NN * 32 + 255) / 256;     // 6250

    __half* wh2 = nullptr;
    __half* wh3 = nullptr;
    cudaGetSymbolAddress((void**)&wh2, g_Wh2);
    cudaGetSymbolAddress((void**)&wh3, g_Wh3);

    // 0: layer-1 node logits + g_we (x3) + histogram + W fp16 conversion
    k_front<<<NA1BLK + HISTBLK + CVTBLK, 256>>>(x, W1, as1, ad1,
                                               We1, ae1, We2, ae2, We3, ae3,
                                               ei, W2, W3);
    // 1: fused prefix scan + CSR scatter
    k_scanbuild<<<scanBlk, 1024>>>(ei, ea);
    // 2: layer-1 attention (writes g_o2 fp16)
    k_attn1<<<attnBlk, 256>>>(x, W1, b1);

    dim3 gGemm(2, MPAD / 128);   // (2, 391)

    // layer 2  (3: gemm is the profiled launch; epilogue writes g_als/g_ald)
    k_gemm_f16<<<gGemm, 256>>>(wh2, as2, ad2);
    k_attn<<<attnBlk, 256>>>(b2, nullptr, 1, 0);

    // layer 3 -> d_out (+ reset counters for next launch)
    k_gemm_f16<<<gGemm, 256>>>(wh3, as3, ad3);
    k_attn<<<attnBlk, 256>>>(b3, out, 2, 1);
}